// round 2
// baseline (speedup 1.0000x reference)
#include <cuda_runtime.h>
#include <cstdint>

// Problem constants
#define BATCH 4
#define SEQ   1024
#define EMB   768
#define HEADS 12
#define HDIM  64
#define SLAB  (SEQ*HDIM)      // 65536 floats per head slab
#define BH    (BATCH*HEADS)   // 48

// Scratch
__device__ float g_RS[BH * HEADS * EMB];   // RS[bh][c][j], c in 0..11  (442K floats)
__device__ float g_G[BATCH * EMB];         // G[b][h*64+d]  (3072 floats)

// ---------------------------------------------------------------------------
// Kernel A: RS[bh][c][j] = sum over rows s of value[b,s,j] where column-group
// c of row s lies inside head-slab h.  One block per (b,h), 768 threads (j).
// ---------------------------------------------------------------------------
__global__ void __launch_bounds__(768) rowsum_kernel(const float* __restrict__ value)
{
    const int bh = blockIdx.x;
    const int b = bh / HEADS, h = bh % HEADS;
    const int j = threadIdx.x;

    const int f0 = h * SLAB;
    const int f1 = f0 + SLAB;
    const int s_lo = f0 / EMB;
    const int s_hi = (f1 - 1) / EMB;

    float acc[12];
    #pragma unroll
    for (int c = 0; c < 12; c++) acc[c] = 0.0f;

    const float* vp = value + (size_t)b * SEQ * EMB + (size_t)s_lo * EMB + j;
    for (int s = s_lo; s <= s_hi; s++, vp += EMB) {
        float v = *vp;
        int rem0 = f0 - s * EMB;                       // need 64c >= rem0
        int rem1 = f1 - s * EMB;                       // need 64c + 64 <= rem1
        int c_lo = (rem0 > 0) ? ((rem0 + 63) >> 6) : 0;
        int c_hi = (rem1 >> 6) - 1;                    // may exceed 11
        #pragma unroll
        for (int c = 0; c < 12; c++)
            if (c >= c_lo && c <= c_hi) acc[c] += v;
    }

    float* out = g_RS + ((size_t)bh * HEADS) * EMB + j;
    #pragma unroll
    for (int c = 0; c < 12; c++) out[c * EMB] = acc[c];
}

// ---------------------------------------------------------------------------
// Kernel B: G[b][h*64+d] = sum_{c,j} Wv[64c+d, j] * RS[bh][c][j]
// Reformulated: for e in 0..767:  G[b][h*64 + (e%64)] += dot(Wv[e,:], RS[bh][e/64,:])
// One block per (b,h), 256 threads; thread tid handles e = tid, tid+256, tid+512
// (all share d = tid % 64), then 4-way reduction across tid%64 classes.
// ---------------------------------------------------------------------------
__global__ void __launch_bounds__(256) head_gemv_kernel(const float* __restrict__ Wv)
{
    const int bh = blockIdx.x;
    const int b = bh / HEADS, h = bh % HEADS;
    const int tid = threadIdx.x;

    __shared__ float RSs[12 * EMB];     // 36 KB
    __shared__ float red[256];

    // cooperative load of RS[bh]
    const float4* src = (const float4*)(g_RS + (size_t)bh * HEADS * EMB);
    float4* dst = (float4*)RSs;
    #pragma unroll
    for (int i = 0; i < (12 * EMB / 4) / 256; i++)
        dst[tid + i * 256] = src[tid + i * 256];
    __syncthreads();

    float sum3 = 0.0f;
    #pragma unroll
    for (int r = 0; r < 3; r++) {
        const int e = tid + r * 256;
        const int c = e >> 6;
        const float4* wrow = (const float4*)(Wv + (size_t)e * EMB);
        const float4* rrow = (const float4*)(RSs + c * EMB);
        float dot = 0.0f;
        #pragma unroll 4
        for (int q = 0; q < EMB / 4; q++) {
            float4 w = wrow[q];
            float4 x = rrow[q];
            dot = fmaf(w.x, x.x, dot);
            dot = fmaf(w.y, x.y, dot);
            dot = fmaf(w.z, x.z, dot);
            dot = fmaf(w.w, x.w, dot);
        }
        sum3 += dot;
    }
    red[tid] = sum3;
    __syncthreads();

    if (tid < 64) {
        float g = red[tid] + red[tid + 64] + red[tid + 128] + red[tid + 192];
        g_G[b * EMB + h * HDIM + tid] = g;
    }
}

// ---------------------------------------------------------------------------
// Kernel C: out[b, q, :] = G[b, :]  for all q   (broadcast 768-vector)
// ---------------------------------------------------------------------------
__global__ void __launch_bounds__(192) broadcast_kernel(float* __restrict__ out)
{
    const int x = blockIdx.x;           // b*1024 + q
    const int b = x >> 10;
    const float4 v = ((const float4*)(g_G + b * EMB))[threadIdx.x];
    ((float4*)(out + (size_t)x * EMB))[threadIdx.x] = v;
}

// ---------------------------------------------------------------------------
extern "C" void kernel_launch(void* const* d_in, const int* in_sizes, int n_in,
                              void* d_out, int out_size)
{
    // metadata order: key, query, value, Wk, Wq, Wv
    const float* value = (const float*)d_in[2];
    const float* Wv    = (const float*)d_in[5];
    float* out = (float*)d_out;

    rowsum_kernel<<<BH, 768>>>(value);
    head_gemv_kernel<<<BH, 256>>>(Wv);
    broadcast_kernel<<<BATCH * SEQ, 192>>>(out);
}

// round 3
// speedup vs baseline: 1.2369x; 1.2369x over previous
#include <cuda_runtime.h>
#include <cstdint>

#define BATCH 4
#define SEQ   1024
#define EMB   768
#define HEADS 12
#define HDIM  64
#define SLAB  (SEQ*HDIM)       // 65536
#define BH    (BATCH*HEADS)    // 48
#define NCH   64               // chunks per batch
#define CHROWS 16              // rows per chunk

// Scratch
__device__ float g_CS[BATCH * NCH * EMB];          // chunk column sums (786 KB)
__device__ float g_RS[BH * HEADS * EMB];           // RS[bh][c][j] (442 KB... actually 48*12*768)
__device__ float g_G[BATCH * EMB];                 // final per-batch vector

// ---------------------------------------------------------------------------
// A: CS[b][k][j] = sum_{s=16k..16k+15} value[b,s,j].  256 blocks x 768 thr.
// ---------------------------------------------------------------------------
__global__ void __launch_bounds__(768) chunk_sum_kernel(const float* __restrict__ value)
{
    const int x = blockIdx.x;            // b*64 + k
    const int b = x >> 6, k = x & 63;
    const int j = threadIdx.x;

    const float* vp = value + ((size_t)b * SEQ + (size_t)k * CHROWS) * EMB + j;
    float acc = 0.0f;
    #pragma unroll
    for (int i = 0; i < CHROWS; i++) acc += vp[i * EMB];
    g_CS[((size_t)b * NCH + k) * EMB + j] = acc;
}

// ---------------------------------------------------------------------------
// B: RS[bh][c][j] = sum over s in [a,bend) of value[b,s,j], via chunk sums +
// edge rows.  576 blocks (bh*12+c) x 768 thr.
// ---------------------------------------------------------------------------
__global__ void __launch_bounds__(768) range_sum_kernel(const float* __restrict__ value)
{
    const int x = blockIdx.x;
    const int bh = x / HEADS;            // 0..47
    const int c  = x % HEADS;            // 0..11
    const int b = bh / HEADS, h = bh % HEADS;
    const int j = threadIdx.x;

    const int f0 = h * SLAB;
    const int f1 = f0 + SLAB;

    // s range: f0 <= 768 s + 64 c  and  768 s + 64 c + 64 <= f1
    int num0 = f0 - 64 * c;
    int a = (num0 <= 0) ? 0 : (num0 + EMB - 1) / EMB;
    int bend = (f1 - 64 * c - 64) / EMB + 1;
    if (bend > SEQ) bend = SEQ;

    const float* vb = value + (size_t)b * SEQ * EMB + j;
    const float* cs = g_CS + (size_t)b * NCH * EMB + j;

    float acc = 0.0f;
    int k_lo = (a + CHROWS - 1) >> 4;
    int k_hi = bend >> 4;

    if (k_lo >= k_hi) {
        for (int s = a; s < bend; s++) acc += vb[(size_t)s * EMB];
    } else {
        for (int k = k_lo; k < k_hi; k++) acc += cs[(size_t)k * EMB];
        const int fa = k_lo << 4;
        for (int s = a; s < fa; s++)     acc += vb[(size_t)s * EMB];
        const int fb = k_hi << 4;
        for (int s = fb; s < bend; s++)  acc += vb[(size_t)s * EMB];
    }

    g_RS[((size_t)bh * HEADS + c) * EMB + j] = acc;
}

// ---------------------------------------------------------------------------
// C: G[b][h*64+d] = sum_c dot(Wv[64c+d,:], RS[bh][c][:]).
// 48 blocks x 768 thr; thread e computes dot(Wv[e], RS[bh][e>>6]), then the
// 12 c-classes sharing d = e&63 are reduced in smem.
// ---------------------------------------------------------------------------
__global__ void __launch_bounds__(768) head_gemv_kernel(const float* __restrict__ Wv)
{
    const int bh = blockIdx.x;
    const int b = bh / HEADS, h = bh % HEADS;
    const int e = threadIdx.x;

    __shared__ float RSs[HEADS * EMB];   // 36 KB
    __shared__ float red[768];

    // load RS[bh] (9216 floats = 2304 float4, 3 per thread)
    {
        const float4* src = (const float4*)(g_RS + (size_t)bh * HEADS * EMB);
        float4* dst = (float4*)RSs;
        #pragma unroll
        for (int i = 0; i < 3; i++) dst[e + i * 768] = src[e + i * 768];
    }
    __syncthreads();

    const int c = e >> 6;
    const float4* wrow = (const float4*)(Wv + (size_t)e * EMB);
    const float4* rrow = (const float4*)(RSs + c * EMB);
    float dot = 0.0f;
    #pragma unroll 8
    for (int q = 0; q < EMB / 4; q++) {
        float4 w = __ldg(&wrow[q]);
        float4 xv = rrow[q];
        dot = fmaf(w.x, xv.x, dot);
        dot = fmaf(w.y, xv.y, dot);
        dot = fmaf(w.z, xv.z, dot);
        dot = fmaf(w.w, xv.w, dot);
    }
    red[e] = dot;
    __syncthreads();

    if (e < HDIM) {
        float g = 0.0f;
        #pragma unroll
        for (int cc = 0; cc < HEADS; cc++) g += red[cc * HDIM + e];
        g_G[b * EMB + h * HDIM + e] = g;
    }
}

// ---------------------------------------------------------------------------
// D: out[b, q, :] = G[b, :]  (broadcast)
// ---------------------------------------------------------------------------
__global__ void __launch_bounds__(192) broadcast_kernel(float* __restrict__ out)
{
    const int x = blockIdx.x;            // b*1024 + q
    const int b = x >> 10;
    const float4 v = ((const float4*)(g_G + b * EMB))[threadIdx.x];
    ((float4*)(out + (size_t)x * EMB))[threadIdx.x] = v;
}

// ---------------------------------------------------------------------------
extern "C" void kernel_launch(void* const* d_in, const int* in_sizes, int n_in,
                              void* d_out, int out_size)
{
    // metadata order: key, query, value, Wk, Wq, Wv
    const float* value = (const float*)d_in[2];
    const float* Wv    = (const float*)d_in[5];
    float* out = (float*)d_out;

    chunk_sum_kernel<<<BATCH * NCH, 768>>>(value);
    range_sum_kernel<<<BH * HEADS, 768>>>(value);
    head_gemv_kernel<<<BH, 768>>>(Wv);
    broadcast_kernel<<<BATCH * SEQ, 192>>>(out);
}

// round 4
// speedup vs baseline: 4.5805x; 3.7031x over previous
#include <cuda_runtime.h>
#include <cstdint>

#define BATCH 4
#define SEQ   1024
#define EMB   768
#define HEADS 12
#define HDIM  64
#define SLAB  (SEQ*HDIM)       // 65536
#define BH    (BATCH*HEADS)    // 48
#define NCH   64               // 16-row chunks per batch
#define CHROWS 16

// Scratch
__device__ float g_CS[BATCH * NCH * EMB];    // chunk column sums
__device__ float g_RS[BH * HEADS * EMB];     // RS[bh][c][j]
__device__ float g_G[BATCH * EMB];           // final per-batch vector (atomically reduced)

// ---------------------------------------------------------------------------
// K0: CS[b][k][j] = sum_{s=16k..16k+15} value[b,s,j].  Block 0 also zeros g_G.
// ---------------------------------------------------------------------------
__global__ void __launch_bounds__(768) chunk_sum_kernel(const float* __restrict__ value)
{
    const int x = blockIdx.x;            // b*64 + k
    const int b = x >> 6, k = x & 63;
    const int j = threadIdx.x;

    if (x == 0) {                        // zero the atomic accumulator
        float4 z = make_float4(0.f, 0.f, 0.f, 0.f);
        ((float4*)g_G)[j] = z;           // 768 float4 = 3072 floats ✓
    }

    const float* vp = value + ((size_t)b * SEQ + (size_t)k * CHROWS) * EMB + j;
    float acc = 0.0f;
    #pragma unroll
    for (int i = 0; i < CHROWS; i++) acc += vp[i * EMB];
    g_CS[((size_t)b * NCH + k) * EMB + j] = acc;
}

// ---------------------------------------------------------------------------
// K1: RS[bh][c][j] = sum over s in [a,bend) of value[b,s,j], via chunk sums +
// edge rows.  576 blocks (bh*12+c) x 768 thr.
// ---------------------------------------------------------------------------
__global__ void __launch_bounds__(768) range_sum_kernel(const float* __restrict__ value)
{
    const int x = blockIdx.x;
    const int bh = x / HEADS;
    const int c  = x % HEADS;
    const int b = bh / HEADS, h = bh % HEADS;
    const int j = threadIdx.x;

    const int f0 = h * SLAB;
    const int f1 = f0 + SLAB;

    int num0 = f0 - 64 * c;
    int a = (num0 <= 0) ? 0 : (num0 + EMB - 1) / EMB;
    int bend = (f1 - 64 * c - 64) / EMB + 1;
    if (bend > SEQ) bend = SEQ;

    const float* vb = value + (size_t)b * SEQ * EMB + j;
    const float* cs = g_CS + (size_t)b * NCH * EMB + j;

    float acc = 0.0f;
    int k_lo = (a + CHROWS - 1) >> 4;
    int k_hi = bend >> 4;

    if (k_lo >= k_hi) {
        for (int s = a; s < bend; s++) acc += vb[(size_t)s * EMB];
    } else {
        for (int k = k_lo; k < k_hi; k++) acc += cs[(size_t)k * EMB];
        const int fa = k_lo << 4;
        for (int s = a; s < fa; s++)     acc += vb[(size_t)s * EMB];
        const int fb = k_hi << 4;
        for (int s = fb; s < bend; s++)  acc += vb[(size_t)s * EMB];
    }

    g_RS[((size_t)bh * HEADS + c) * EMB + j] = acc;
}

// ---------------------------------------------------------------------------
// K2: K-split GEMM.  grid = 144 blocks (c = blk/12, jt = blk%12), 256 threads.
// Each block: Ws = Wv[64c..64c+63][jt*64..+63]   (64x64)
//             As = RS[0..47][c][jt*64..+63]      (48x64)
//             partial[bh][d] = sum_k As[bh][k]*Ws[d][k]  -> atomicAdd g_G
// ---------------------------------------------------------------------------
__global__ void __launch_bounds__(256) kgemm_kernel(const float* __restrict__ Wv)
{
    const int c  = blockIdx.x / 12;
    const int jt = blockIdx.x % 12;
    const int t = threadIdx.x;

    __shared__ float Ws[64][65];
    __shared__ float As[48][65];

    // load Wv slice: 64 rows x 16 float4
    #pragma unroll
    for (int i = 0; i < 4; i++) {
        int f = t + 256 * i;
        int r = f >> 4, c4 = f & 15;
        float4 v = *(const float4*)(Wv + (size_t)(64 * c + r) * EMB + jt * 64 + c4 * 4);
        Ws[r][c4 * 4 + 0] = v.x; Ws[r][c4 * 4 + 1] = v.y;
        Ws[r][c4 * 4 + 2] = v.z; Ws[r][c4 * 4 + 3] = v.w;
    }
    // load RS slice: 48 rows x 16 float4
    #pragma unroll
    for (int i = 0; i < 3; i++) {
        int f = t + 256 * i;
        int r = f >> 4, c4 = f & 15;
        float4 v = *(const float4*)(g_RS + ((size_t)r * HEADS + c) * EMB + jt * 64 + c4 * 4);
        As[r][c4 * 4 + 0] = v.x; As[r][c4 * 4 + 1] = v.y;
        As[r][c4 * 4 + 2] = v.z; As[r][c4 * 4 + 3] = v.w;
    }
    __syncthreads();

    const int tx = t & 15;     // d group: 4 d's
    const int ty = t >> 4;     // bh group: 3 bh's

    float acc[3][4] = {};
    #pragma unroll 8
    for (int k = 0; k < 64; k++) {
        float a[3], bb[4];
        #pragma unroll
        for (int u = 0; u < 3; u++) a[u] = As[ty * 3 + u][k];
        #pragma unroll
        for (int v = 0; v < 4; v++) bb[v] = Ws[tx * 4 + v][k];
        #pragma unroll
        for (int u = 0; u < 3; u++)
            #pragma unroll
            for (int v = 0; v < 4; v++)
                acc[u][v] = fmaf(a[u], bb[v], acc[u][v]);
    }

    #pragma unroll
    for (int u = 0; u < 3; u++) {
        int bh = ty * 3 + u;
        int b = bh / HEADS, h = bh % HEADS;
        float* gp = g_G + b * EMB + h * HDIM + tx * 4;
        #pragma unroll
        for (int v = 0; v < 4; v++)
            atomicAdd(gp + v, acc[u][v]);
    }
}

// ---------------------------------------------------------------------------
// K3: out[b, q, :] = G[b, :]   512 blocks x 768 thr, 8 rows per block.
// ---------------------------------------------------------------------------
__global__ void __launch_bounds__(768) broadcast_kernel(float* __restrict__ out)
{
    const int t = threadIdx.x;
    const int row0 = blockIdx.x * 8;           // 4096 rows total
    const int c4 = t % 192;                    // float4 column
    const int r  = t / 192;                    // 0..3

    const int row = row0 + r;                  // rows row, row+4
    const int b0 = (row)     >> 10;
    const int b1 = (row + 4) >> 10;

    float4 v0 = ((const float4*)(g_G + b0 * EMB))[c4];
    ((float4*)(out + (size_t)row * EMB))[c4] = v0;

    float4 v1 = (b1 == b0) ? v0 : ((const float4*)(g_G + b1 * EMB))[c4];
    ((float4*)(out + (size_t)(row + 4) * EMB))[c4] = v1;
}

// ---------------------------------------------------------------------------
extern "C" void kernel_launch(void* const* d_in, const int* in_sizes, int n_in,
                              void* d_out, int out_size)
{
    // metadata order: key, query, value, Wk, Wq, Wv
    const float* value = (const float*)d_in[2];
    const float* Wv    = (const float*)d_in[5];
    float* out = (float*)d_out;

    chunk_sum_kernel<<<BATCH * NCH, 768>>>(value);
    range_sum_kernel<<<BH * HEADS, 768>>>(value);
    kgemm_kernel<<<144, 256>>>(Wv);
    broadcast_kernel<<<512, 768>>>(out);
}